// round 6
// baseline (speedup 1.0000x reference)
#include <cuda_runtime.h>
#include <cstdint>

#define BATCH 4096
#define S_SZ  200
#define D_SZ  256

// ---- main-kernel dynamic SMEM word map ----
#define XH_W     0          // 13*16*32*4 = 26624 words: X_hi fragments
#define XL_W     26624      // X_lo fragments
#define SC_W     53248      // 256 f32 combined bias
#define SCORE_W  53504      // 208 f32
#define SRED_W   53712      // 32 f32
#define SMEM_WORDS 53744
#define SMEM_BYTES (SMEM_WORDS * 4)

__device__ float g_catep[BATCH * D_SZ];
__device__ int   g_mask_mode;                 // 0=u8, 1=i32, 2=f32
__device__ uint4 g_w1pk[32 * 16 * 32];        // 256 KB packed W1 fragments

__device__ __forceinline__ unsigned pack_bf2(float lo, float hi) {
    unsigned r;
    asm("cvt.rn.bf16x2.f32 %0, %1, %2;" : "=r"(r) : "f"(hi), "f"(lo));
    return r;
}
__device__ __forceinline__ float bf_lo(unsigned w) { return __uint_as_float(w << 16); }
__device__ __forceinline__ float bf_hi(unsigned w) { return __uint_as_float(w & 0xFFFF0000u); }
__device__ __forceinline__ float sigf(float x) { return __fdividef(1.0f, 1.0f + __expf(-x)); }

#define MMA16816(d, a0, a1, a2, a3, b0, b1)                                   \
    asm volatile("mma.sync.aligned.m16n8k16.row.col.f32.bf16.bf16.f32 "       \
                 "{%0,%1,%2,%3}, {%4,%5,%6,%7}, {%8,%9}, {%0,%1,%2,%3};"      \
                 : "+f"(d[0]), "+f"(d[1]), "+f"(d[2]), "+f"(d[3])             \
                 : "r"(a0), "r"(a1), "r"(a2), "r"(a3), "r"(b0), "r"(b1))

// ---------------------------------------------------------------------------
// Prep kernel (one launch): blocks 0..255 = catep GEMM, 256 = W1 fragment
// packing, 257 = mask dtype detection.
// ---------------------------------------------------------------------------
__global__ void prep_kernel(const float* __restrict__ cate,
                            const float* __restrict__ W2,
                            const float* __restrict__ b2,
                            const float* __restrict__ W1,
                            const unsigned* __restrict__ mw) {
    __shared__ float sm[16 * 256];
    __shared__ int   fl[2];
    const int blk = blockIdx.x, tid = threadIdx.x;

    if (blk < 256) {
        const int bbase = blk * 16;
        #pragma unroll
        for (int i = 0; i < 16; i++)
            sm[i * 256 + tid] = cate[(size_t)(bbase + i) * 256 + tid];
        __syncthreads();

        float acc[16];
        #pragma unroll
        for (int r = 0; r < 16; r++) acc[r] = 0.0f;
        const float* w2row = W2 + (size_t)tid * 256;
        #pragma unroll 4
        for (int k = 0; k < 256; k++) {
            const float w = w2row[k];
            #pragma unroll
            for (int r = 0; r < 16; r++) acc[r] += sm[r * 256 + k] * w;
        }
        const float bias = b2[tid];
        #pragma unroll
        for (int r = 0; r < 16; r++)
            g_catep[(size_t)(bbase + r) * 256 + tid] = acc[r] + bias;
    } else if (blk == 256) {
        // W1 -> per-lane packed bf16 hi/lo fragments.
        // entry e = (ntg*16 + kt)*32 + lane ; lane = qr*4 + qc
        for (int e = tid; e < 32 * 16 * 32; e += 256) {
            const int ntg = e >> 9, kt = (e >> 5) & 15, lane = e & 31;
            const int qr = lane >> 2, qc = lane & 3;
            const float* src = W1 + (size_t)(ntg * 8 + qr) * 256 + kt * 16 + 2 * qc;
            const float w0 = src[0], w1v = src[1], w8 = src[8], w9 = src[9];
            const unsigned bh0 = pack_bf2(w0, w1v);
            const unsigned bh1 = pack_bf2(w8, w9);
            const unsigned bl0 = pack_bf2(w0 - bf_lo(bh0), w1v - bf_hi(bh0));
            const unsigned bl1 = pack_bf2(w8 - bf_lo(bh1), w9 - bf_hi(bh1));
            g_w1pk[e] = make_uint4(bh0, bh1, bl0, bl1);
        }
    } else {
        if (tid == 0) { fl[0] = 0; fl[1] = 0; }
        __syncthreads();
        int lF = 0, lU = 0;
        for (int i = tid; i < 4096; i += 256) {
            const unsigned v = mw[i];
            if (v == 0x3F800000u) lF = 1;
            if (v & 0xFFFFFF00u)  lU = 1;
        }
        if (lF) fl[0] = 1;
        if (lU) fl[1] = 1;
        __syncthreads();
        if (tid == 0) g_mask_mode = fl[0] ? 2 : (fl[1] ? 0 : 1);
    }
}

// ---------------------------------------------------------------------------
// GEMM worker: warp covers m-tiles [mt0, mt0+NMT) and n-cols [wn*64, wn*64+64)
// in 2 passes of n=32. A-frags reused across 4 n-tiles -> LDS traffic halved.
// ---------------------------------------------------------------------------
template <int NMT>
__device__ __forceinline__ void gemm_part(const unsigned* __restrict__ sw,
                                          float* sScore, const float* sC,
                                          int mt0, int wn, int lane) {
    const int qr = lane >> 2, qc = lane & 3;

    #pragma unroll 1
    for (int p = 0; p < 2; p++) {
        const int n0   = wn * 64 + p * 32;
        const int ntg0 = n0 >> 3;

        float acc[NMT][4][4];
        #pragma unroll
        for (int mt = 0; mt < NMT; mt++)
            #pragma unroll
            for (int j = 0; j < 4; j++)
                #pragma unroll
                for (int i = 0; i < 4; i++) acc[mt][j][i] = 0.0f;

        // B-fragment double buffer (hide L2 latency)
        uint4 wq[4];
        #pragma unroll
        for (int j = 0; j < 4; j++)
            wq[j] = g_w1pk[(size_t)((ntg0 + j) * 16) * 32 + lane];

        #pragma unroll 1
        for (int kt = 0; kt < 16; kt++) {
            uint4 w[4];
            #pragma unroll
            for (int j = 0; j < 4; j++) w[j] = wq[j];
            if (kt < 15) {
                #pragma unroll
                for (int j = 0; j < 4; j++)
                    wq[j] = g_w1pk[(size_t)((ntg0 + j) * 16 + kt + 1) * 32 + lane];
            }
            const unsigned abase = kt * 128 + lane * 4;
            #pragma unroll
            for (int mt = 0; mt < NMT; mt++) {
                const uint4 ah = *(const uint4*)(sw + XH_W + (mt0 + mt) * 2048 + abase);
                const uint4 al = *(const uint4*)(sw + XL_W + (mt0 + mt) * 2048 + abase);
                // dependency spacing 4 on each acc[j]
                #pragma unroll
                for (int j = 0; j < 4; j++)
                    MMA16816(acc[mt][j], ah.x, ah.y, ah.z, ah.w, w[j].x, w[j].y);
                #pragma unroll
                for (int j = 0; j < 4; j++)
                    MMA16816(acc[mt][j], ah.x, ah.y, ah.z, ah.w, w[j].z, w[j].w);
                #pragma unroll
                for (int j = 0; j < 4; j++)
                    MMA16816(acc[mt][j], al.x, al.y, al.z, al.w, w[j].x, w[j].y);
            }
        }

        // epilogue: sigmoid + per-row partial sums -> smem atomics
        float b0[4], b1[4];
        #pragma unroll
        for (int j = 0; j < 4; j++) {
            b0[j] = sC[n0 + j * 8 + 2 * qc];
            b1[j] = sC[n0 + j * 8 + 2 * qc + 1];
        }
        #pragma unroll
        for (int mt = 0; mt < NMT; mt++) {
            float v0 = 0.0f, v1 = 0.0f;
            #pragma unroll
            for (int j = 0; j < 4; j++) {
                v0 += sigf(acc[mt][j][0] + b0[j]) + sigf(acc[mt][j][1] + b1[j]);
                v1 += sigf(acc[mt][j][2] + b0[j]) + sigf(acc[mt][j][3] + b1[j]);
            }
            v0 += __shfl_xor_sync(0xffffffffu, v0, 1);
            v0 += __shfl_xor_sync(0xffffffffu, v0, 2);
            v1 += __shfl_xor_sync(0xffffffffu, v1, 1);
            v1 += __shfl_xor_sync(0xffffffffu, v1, 2);
            if (qc == 0) {
                atomicAdd(&sScore[(mt0 + mt) * 16 + qr], v0);
                atomicAdd(&sScore[(mt0 + mt) * 16 + qr + 8], v1);
            }
        }
    }
}

// ---------------------------------------------------------------------------
// Main fused kernel: one CTA (256 thr) per batch.
// ---------------------------------------------------------------------------
__global__ void __launch_bounds__(256, 1)
hba_main_kernel(const float* __restrict__ seq,
                const void*  __restrict__ maskp,
                const float* __restrict__ b1,
                float* __restrict__ out) {
    extern __shared__ unsigned sw[];
    const int b = blockIdx.x, tid = threadIdx.x;
    const int warp = tid >> 5, lane = tid & 31;

    float* sC     = (float*)(sw + SC_W);
    float* sScore = (float*)(sw + SCORE_W);
    float* sRed   = (float*)(sw + SRED_W);

    // early gmem loads (hidden behind P1/P2)
    bool mk = false;
    if (tid < S_SZ) {
        const size_t mi = (size_t)b * S_SZ + tid;
        const int mode = g_mask_mode;
        if (mode == 0)      mk = ((const unsigned char*)maskp)[mi] != 0;
        else if (mode == 1) mk = ((const int*)maskp)[mi] != 0;
        else                mk = ((const float*)maskp)[mi] != 0.0f;
    }

    sC[tid] = g_catep[(size_t)b * 256 + tid] + b1[tid];
    if (tid < 208) sScore[tid] = 0.0f;
    // zero mt=12 pad block (rows 192..207; 192..199 overwritten below)
    for (int i = tid; i < 2048; i += 256) {
        sw[XH_W + 24576 + i] = 0u;
        sw[XL_W + 24576 + i] = 0u;
    }
    __syncthreads();

    // ---- P1: load + split into fragment order ----
    {
        const float4* gsrc = (const float4*)(seq + (size_t)b * S_SZ * D_SZ);
        for (int idx = tid; idx < S_SZ * 64; idx += 256) {
            const int r = idx >> 6, c4 = idx & 63;
            const float4 v = gsrc[idx];
            const unsigned h01 = pack_bf2(v.x, v.y);
            const unsigned h23 = pack_bf2(v.z, v.w);
            const unsigned l01 = pack_bf2(v.x - bf_lo(h01), v.y - bf_hi(h01));
            const unsigned l23 = pack_bf2(v.z - bf_lo(h23), v.w - bf_hi(h23));
            const int cp = 2 * c4, rr = cp & 7;
            const int r16 = r & 15;
            const int widx = (r >> 4) * 2048 + (cp >> 3) * 128
                           + (r16 & 7) * 16 + (rr & 3) * 4 + (rr >> 2) * 2 + (r16 >> 3);
            sw[XH_W + widx]     = h01;
            sw[XH_W + widx + 4] = h23;
            sw[XL_W + widx]     = l01;
            sw[XL_W + widx + 4] = l23;
        }
    }
    __syncthreads();

    // ---- P2: GEMM. warps 0-3: mt 0-6; warps 4-7: mt 7-12; n = (warp&3)*64 ----
    if (warp < 4) gemm_part<7>(sw, sScore, sC, 0, warp, lane);
    else          gemm_part<6>(sw, sScore, sC, 7, warp & 3, lane);
    __syncthreads();

    // ---- P3: mask + softmax over S ----
    float sv = -3.4e38f;
    if (tid < S_SZ) sv = mk ? -1e9f : sScore[tid];

    float m = sv;
    #pragma unroll
    for (int o = 16; o > 0; o >>= 1) m = fmaxf(m, __shfl_xor_sync(0xffffffffu, m, o));
    if (lane == 0) sRed[warp] = m;
    __syncthreads();
    if (warp == 0) {
        float t = (lane < 8) ? sRed[lane] : -3.4e38f;
        #pragma unroll
        for (int o = 16; o > 0; o >>= 1) t = fmaxf(t, __shfl_xor_sync(0xffffffffu, t, o));
        if (lane == 0) sRed[16] = t;
    }
    __syncthreads();
    m = sRed[16];

    const float ev = (tid < S_SZ) ? __expf(sv - m) : 0.0f;
    float l = ev;
    #pragma unroll
    for (int o = 16; o > 0; o >>= 1) l += __shfl_xor_sync(0xffffffffu, l, o);
    if (lane == 0) sRed[warp] = l;
    __syncthreads();
    if (warp == 0) {
        float u = (lane < 8) ? sRed[lane] : 0.0f;
        #pragma unroll
        for (int o = 16; o > 0; o >>= 1) u += __shfl_xor_sync(0xffffffffu, u, o);
        if (lane == 0) sRed[17] = u;
    }
    if (tid < S_SZ) sScore[tid] = ev;
    __syncthreads();
    const float inv = 1.0f / sRed[17];

    // ---- P4: pooling from fragment layout (x = hi + lo) ----
    {
        const int cp = tid >> 1, hl = tid & 1;
        const int Cd = (cp >> 3) * 128 + (cp & 3) * 4 + ((cp & 7) >> 2) * 2;
        float accd = 0.0f;
        #pragma unroll 4
        for (int s = 0; s < S_SZ; s++) {
            const int fs = (s >> 4) * 2048 + (s & 7) * 16 + ((s & 15) >> 3);
            const unsigned wh = sw[XH_W + Cd + fs];
            const unsigned wl = sw[XL_W + Cd + fs];
            const float x = (hl ? bf_hi(wh) : bf_lo(wh)) + (hl ? bf_hi(wl) : bf_lo(wl));
            accd += sScore[s] * x;
        }
        out[(size_t)b * 256 + tid] = accd * inv;
    }
}

// ---------------------------------------------------------------------------
extern "C" void kernel_launch(void* const* d_in, const int* in_sizes, int n_in,
                              void* d_out, int out_size) {
    const float* cate = (const float*)d_in[0];
    const float* seq  = (const float*)d_in[1];
    const void*  mask = d_in[2];
    const float* W1   = (const float*)d_in[3];
    const float* b1   = (const float*)d_in[4];
    const float* W2   = (const float*)d_in[5];
    const float* b2   = (const float*)d_in[6];
    float*       out  = (float*)d_out;

    cudaFuncSetAttribute(hba_main_kernel,
                         cudaFuncAttributeMaxDynamicSharedMemorySize, SMEM_BYTES);

    prep_kernel<<<258, 256>>>(cate, W2, b2, W1, (const unsigned*)mask);
    hba_main_kernel<<<BATCH, 256, SMEM_BYTES>>>(seq, mask, b1, out);
}

// round 8
// speedup vs baseline: 1.2360x; 1.2360x over previous
#include <cuda_runtime.h>
#include <cuda_fp16.h>
#include <cstdint>

#define BATCH 4096
#define S_SZ  200
#define D_SZ  256

// ---- K_score dynamic SMEM word map (max NMT=5) ----
#define XH_W     0          // 5*2048 words: X_hi fp16 fragments
#define XL_W     10240      // X_lo fragments
#define SC_W     20480      // 256 f32 combined bias
#define SCORE_W  20736      // 80 f32 partial row sums
#define SMEM_WORDS 20816
#define SMEM_BYTES (SMEM_WORDS * 4)

__device__ float g_catep[BATCH * D_SZ];
__device__ float g_scores[BATCH * S_SZ];
__device__ int   g_mask_mode;                 // 0=u8, 1=i32, 2=f32
__device__ uint4 g_w1pk[32 * 16 * 32];        // 256 KB packed fp16 W hi/lo fragments

__device__ __forceinline__ unsigned pack_hf2(float lo, float hi) {
    unsigned r;
    asm("cvt.rn.f16x2.f32 %0, %1, %2;" : "=r"(r) : "f"(hi), "f"(lo));
    return r;
}
__device__ __forceinline__ float sigf(float x) { return __fdividef(1.0f, 1.0f + __expf(-x)); }

#define MMAF16(d, a0, a1, a2, a3, b0, b1)                                     \
    asm volatile("mma.sync.aligned.m16n8k16.row.col.f32.f16.f16.f32 "         \
                 "{%0,%1,%2,%3}, {%4,%5,%6,%7}, {%8,%9}, {%0,%1,%2,%3};"      \
                 : "+f"(d[0]), "+f"(d[1]), "+f"(d[2]), "+f"(d[3])             \
                 : "r"(a0), "r"(a1), "r"(a2), "r"(a3), "r"(b0), "r"(b1))

// ---------------------------------------------------------------------------
// Prep: blocks 0..255 = catep GEMM (fp32 exact), 256 = W1 fp16 hi/lo fragment
// pack, 257 = mask dtype detection.
// ---------------------------------------------------------------------------
__global__ void prep_kernel(const float* __restrict__ cate,
                            const float* __restrict__ W2,
                            const float* __restrict__ b2,
                            const float* __restrict__ W1,
                            const unsigned* __restrict__ mw) {
    __shared__ float sm[16 * 256];
    __shared__ int   fl[2];
    const int blk = blockIdx.x, tid = threadIdx.x;

    if (blk < 256) {
        const int bbase = blk * 16;
        #pragma unroll
        for (int i = 0; i < 16; i++)
            sm[i * 256 + tid] = cate[(size_t)(bbase + i) * 256 + tid];
        __syncthreads();

        float acc[16];
        #pragma unroll
        for (int r = 0; r < 16; r++) acc[r] = 0.0f;
        const float* w2row = W2 + (size_t)tid * 256;
        #pragma unroll 4
        for (int k = 0; k < 256; k++) {
            const float w = w2row[k];
            #pragma unroll
            for (int r = 0; r < 16; r++) acc[r] += sm[r * 256 + k] * w;
        }
        const float bias = b2[tid];
        #pragma unroll
        for (int r = 0; r < 16; r++)
            g_catep[(size_t)(bbase + r) * 256 + tid] = acc[r] + bias;
    } else if (blk == 256) {
        // entry e = (ntg*16 + kt)*32 + lane ; lane = qr*4 + qc
        for (int e = tid; e < 32 * 16 * 32; e += 256) {
            const int ntg = e >> 9, kt = (e >> 5) & 15, lane = e & 31;
            const int qr = lane >> 2, qc = lane & 3;
            const float* src = W1 + (size_t)(ntg * 8 + qr) * 256 + kt * 16 + 2 * qc;
            const float w0 = src[0], w1v = src[1], w8 = src[8], w9 = src[9];
            const unsigned h0 = pack_hf2(w0, w1v);
            const unsigned h1 = pack_hf2(w8, w9);
            const float2 f0 = __half22float2(*(const __half2*)&h0);
            const float2 f1 = __half22float2(*(const __half2*)&h1);
            const unsigned l0 = pack_hf2(w0 - f0.x, w1v - f0.y);
            const unsigned l1 = pack_hf2(w8 - f1.x, w9 - f1.y);
            g_w1pk[e] = make_uint4(h0, h1, l0, l1);
        }
    } else {
        if (tid == 0) { fl[0] = 0; fl[1] = 0; }
        __syncthreads();
        int lF = 0, lU = 0;
        for (int i = tid; i < 4096; i += 256) {
            const unsigned v = mw[i];
            if (v == 0x3F800000u) lF = 1;
            if (v & 0xFFFFFF00u)  lU = 1;
        }
        if (lF) fl[0] = 1;
        if (lU) fl[1] = 1;
        __syncthreads();
        if (tid == 0) g_mask_mode = fl[0] ? 2 : (fl[1] ? 0 : 1);
    }
}

// ---------------------------------------------------------------------------
// GEMM worker: NMT m-tiles starting at local tile mtb, n-range [n0, n0+32).
// 3-term fp16: z = Xh@Wh + Xl@Wh + Xh@Wl  (drops only Xl@Wl ~ 1e-9)
// ---------------------------------------------------------------------------
template <int NMT>
__device__ __forceinline__ void gemm_frag(const unsigned* __restrict__ sw,
                                          float* sScore, const float* sC,
                                          int mtb, int n0, int lane) {
    const int qr = lane >> 2, qc = lane & 3;
    const int ntg0 = n0 >> 3;

    float acc[NMT][4][4];
    #pragma unroll
    for (int mt = 0; mt < NMT; mt++)
        #pragma unroll
        for (int j = 0; j < 4; j++)
            #pragma unroll
            for (int i = 0; i < 4; i++) acc[mt][j][i] = 0.0f;

    uint4 wq[4];
    #pragma unroll
    for (int j = 0; j < 4; j++)
        wq[j] = g_w1pk[(size_t)((ntg0 + j) * 16) * 32 + lane];

    #pragma unroll 1
    for (int kt = 0; kt < 16; kt++) {
        uint4 w[4];
        #pragma unroll
        for (int j = 0; j < 4; j++) w[j] = wq[j];
        if (kt < 15) {
            #pragma unroll
            for (int j = 0; j < 4; j++)
                wq[j] = g_w1pk[(size_t)((ntg0 + j) * 16 + kt + 1) * 32 + lane];
        }
        const unsigned abase = kt * 128 + lane * 4;
        #pragma unroll
        for (int mt = 0; mt < NMT; mt++) {
            const uint4 ah = *(const uint4*)(sw + XH_W + (mtb + mt) * 2048 + abase);
            const uint4 al = *(const uint4*)(sw + XL_W + (mtb + mt) * 2048 + abase);
            #pragma unroll
            for (int j = 0; j < 4; j++)
                MMAF16(acc[mt][j], ah.x, ah.y, ah.z, ah.w, w[j].x, w[j].y);
            #pragma unroll
            for (int j = 0; j < 4; j++)
                MMAF16(acc[mt][j], al.x, al.y, al.z, al.w, w[j].x, w[j].y);
            #pragma unroll
            for (int j = 0; j < 4; j++)
                MMAF16(acc[mt][j], ah.x, ah.y, ah.z, ah.w, w[j].z, w[j].w);
        }
    }

    float b0[4], b1[4];
    #pragma unroll
    for (int j = 0; j < 4; j++) {
        b0[j] = sC[n0 + j * 8 + 2 * qc];
        b1[j] = sC[n0 + j * 8 + 2 * qc + 1];
    }
    #pragma unroll
    for (int mt = 0; mt < NMT; mt++) {
        float v0 = 0.0f, v1 = 0.0f;
        #pragma unroll
        for (int j = 0; j < 4; j++) {
            v0 += sigf(acc[mt][j][0] + b0[j]) + sigf(acc[mt][j][1] + b1[j]);
            v1 += sigf(acc[mt][j][2] + b0[j]) + sigf(acc[mt][j][3] + b1[j]);
        }
        v0 += __shfl_xor_sync(0xffffffffu, v0, 1);
        v0 += __shfl_xor_sync(0xffffffffu, v0, 2);
        v1 += __shfl_xor_sync(0xffffffffu, v1, 1);
        v1 += __shfl_xor_sync(0xffffffffu, v1, 2);
        if (qc == 0) {
            atomicAdd(&sScore[(mtb + mt) * 16 + qr], v0);
            atomicAdd(&sScore[(mtb + mt) * 16 + qr + 8], v1);
        }
    }
}

// ---------------------------------------------------------------------------
// K_score: 3 CTAs per batch (m-tiles 5/4/4 -> rows 0-79 / 80-143 / 144-207).
// 81 KB smem, 2 CTAs/SM -> load/epilogue of one CTA overlaps GEMM of other.
// ---------------------------------------------------------------------------
__global__ void __launch_bounds__(256, 2)
score_kernel(const float* __restrict__ seq,
             const float* __restrict__ b1) {
    extern __shared__ unsigned sw[];
    const int bid = blockIdx.x;
    const int b = bid / 3, third = bid - 3 * b;
    const int r0  = (third == 0) ? 0 : (third == 1 ? 80 : 144);
    const int nmt = (third == 0) ? 5 : 4;
    const int tid = threadIdx.x, warp = tid >> 5, lane = tid & 31;

    float* sC     = (float*)(sw + SC_W);
    float* sScore = (float*)(sw + SCORE_W);

    sC[tid] = g_catep[(size_t)b * 256 + tid] + b1[tid];
    if (tid < 80) sScore[tid] = 0.0f;
    __syncthreads();

    // ---- P1: load rows [r0, r0+16*nmt) + fp16 hi/lo split, fragment order ----
    {
        const float4* gsrc = (const float4*)(seq + (size_t)b * S_SZ * D_SZ);
        const int nidx = nmt * 16 * 64;
        for (int idx = tid; idx < nidx; idx += 256) {
            const int lr = idx >> 6, c4 = idx & 63;
            const int g = r0 + lr;
            float4 v = make_float4(0.f, 0.f, 0.f, 0.f);
            if (g < S_SZ) v = gsrc[g * 64 + c4];
            const unsigned h01 = pack_hf2(v.x, v.y);
            const unsigned h23 = pack_hf2(v.z, v.w);
            const float2 f01 = __half22float2(*(const __half2*)&h01);
            const float2 f23 = __half22float2(*(const __half2*)&h23);
            const unsigned l01 = pack_hf2(v.x - f01.x, v.y - f01.y);
            const unsigned l23 = pack_hf2(v.z - f23.x, v.w - f23.y);
            const int cp = 2 * c4, rr = cp & 7;
            const int r16 = lr & 15;
            const int widx = (lr >> 4) * 2048 + (cp >> 3) * 128
                           + (r16 & 7) * 16 + (rr & 3) * 4 + (rr >> 2) * 2 + (r16 >> 3);
            sw[XH_W + widx]     = h01;
            sw[XH_W + widx + 4] = h23;
            sw[XL_W + widx]     = l01;
            sw[XL_W + widx + 4] = l23;
        }
    }
    __syncthreads();

    // ---- P2: GEMM. 2 n-passes of 32; warps 0-3 front m-tiles, 4-7 back ----
    const int n0 = (warp & 3) * 64;
    if (nmt == 5) {
        if (warp < 4) { gemm_frag<3>(sw, sScore, sC, 0, n0,      lane);
                        gemm_frag<3>(sw, sScore, sC, 0, n0 + 32, lane); }
        else          { gemm_frag<2>(sw, sScore, sC, 3, n0,      lane);
                        gemm_frag<2>(sw, sScore, sC, 3, n0 + 32, lane); }
    } else {
        if (warp < 4) { gemm_frag<2>(sw, sScore, sC, 0, n0,      lane);
                        gemm_frag<2>(sw, sScore, sC, 0, n0 + 32, lane); }
        else          { gemm_frag<2>(sw, sScore, sC, 2, n0,      lane);
                        gemm_frag<2>(sw, sScore, sC, 2, n0 + 32, lane); }
    }
    __syncthreads();

    // ---- write this CTA's score rows ----
    if (tid < nmt * 16) {
        const int s = r0 + tid;
        if (s < S_SZ) g_scores[(size_t)b * S_SZ + s] = sScore[tid];
    }
}

// ---------------------------------------------------------------------------
// K_pool: per batch -- mask + softmax over S, then attn-weighted sum pooling
// streaming seq from HBM (exact fp32 x).
// ---------------------------------------------------------------------------
__global__ void __launch_bounds__(256)
pool_kernel(const float* __restrict__ seq,
            const void*  __restrict__ maskp,
            float* __restrict__ out) {
    __shared__ float  sScore[256];   // 256: every thread may write its slot
    __shared__ float  sRed[20];
    __shared__ float4 sPool[256];
    const int b = blockIdx.x, tid = threadIdx.x;
    const int warp = tid >> 5, lane = tid & 31;

    float sv = -3.4e38f;
    if (tid < S_SZ) {
        const size_t mi = (size_t)b * S_SZ + tid;
        const int mode = g_mask_mode;
        bool mk;
        if (mode == 0)      mk = ((const unsigned char*)maskp)[mi] != 0;
        else if (mode == 1) mk = ((const int*)maskp)[mi] != 0;
        else                mk = ((const float*)maskp)[mi] != 0.0f;
        sv = mk ? -1e9f : g_scores[(size_t)b * S_SZ + tid];
    }

    float m = sv;
    #pragma unroll
    for (int o = 16; o > 0; o >>= 1) m = fmaxf(m, __shfl_xor_sync(0xffffffffu, m, o));
    if (lane == 0) sRed[warp] = m;
    __syncthreads();
    if (warp == 0) {
        float t = (lane < 8) ? sRed[lane] : -3.4e38f;
        #pragma unroll
        for (int o = 16; o > 0; o >>= 1) t = fmaxf(t, __shfl_xor_sync(0xffffffffu, t, o));
        if (lane == 0) sRed[16] = t;
    }
    __syncthreads();
    m = sRed[16];

    const float ev = (tid < S_SZ) ? __expf(sv - m) : 0.0f;
    float l = ev;
    #pragma unroll
    for (int o = 16; o > 0; o >>= 1) l += __shfl_xor_sync(0xffffffffu, l, o);
    if (lane == 0) sRed[warp] = l;
    __syncthreads();
    if (warp == 0) {
        float u = (lane < 8) ? sRed[lane] : 0.0f;
        #pragma unroll
        for (int o = 16; o > 0; o >>= 1) u += __shfl_xor_sync(0xffffffffu, u, o);
        if (lane == 0) sRed[17] = u;
    }
    __syncthreads();           // sRed[17] final before sScore writes land
    sScore[tid] = ev;          // tid >= S_SZ wrote ev = 0
    __syncthreads();
    const float inv = 1.0f / sRed[17];

    // ---- pooling: thread (so, j) sums s = so, so+4, ... over d4-group j ----
    const int j = tid & 63, so = tid >> 6;
    const float4* seqv = (const float4*)(seq + (size_t)b * S_SZ * D_SZ);
    float4 acc = make_float4(0.f, 0.f, 0.f, 0.f);
    #pragma unroll 4
    for (int s = so; s < S_SZ; s += 4) {
        const float a = sScore[s];
        const float4 v = seqv[s * 64 + j];
        acc.x += a * v.x; acc.y += a * v.y; acc.z += a * v.z; acc.w += a * v.w;
    }
    sPool[so * 64 + j] = acc;
    __syncthreads();
    if (tid < 64) {
        const float4 p0 = sPool[tid], p1 = sPool[64 + tid];
        const float4 p2 = sPool[128 + tid], p3 = sPool[192 + tid];
        float4 r;
        r.x = (p0.x + p1.x + p2.x + p3.x) * inv;
        r.y = (p0.y + p1.y + p2.y + p3.y) * inv;
        r.z = (p0.z + p1.z + p2.z + p3.z) * inv;
        r.w = (p0.w + p1.w + p2.w + p3.w) * inv;
        ((float4*)out)[(size_t)b * 64 + tid] = r;
    }
}

// ---------------------------------------------------------------------------
extern "C" void kernel_launch(void* const* d_in, const int* in_sizes, int n_in,
                              void* d_out, int out_size) {
    const float* cate = (const float*)d_in[0];
    const float* seq  = (const float*)d_in[1];
    const void*  mask = d_in[2];
    const float* W1   = (const float*)d_in[3];
    const float* b1   = (const float*)d_in[4];
    const float* W2   = (const float*)d_in[5];
    const float* b2   = (const float*)d_in[6];
    float*       out  = (float*)d_out;

    cudaFuncSetAttribute(score_kernel,
                         cudaFuncAttributeMaxDynamicSharedMemorySize, SMEM_BYTES);

    prep_kernel<<<258, 256>>>(cate, W2, b2, W1, (const unsigned*)mask);
    score_kernel<<<3 * BATCH, 256, SMEM_BYTES>>>(seq, b1);
    pool_kernel<<<BATCH, 256>>>(seq, mask, out);
}

// round 11
// speedup vs baseline: 1.4099x; 1.1407x over previous
#include <cuda_runtime.h>
#include <cuda_fp16.h>
#include <cstdint>

#define BATCH 4096
#define S_SZ  200
#define D_SZ  256

// ---- K_score dynamic SMEM word map (max NMT=5) ----
#define XH_W     0          // 5*2048 words: X_hi fp16 fragments
#define XL_W     10240      // X_lo fragments
#define SC_W     20480      // 256 f32 combined bias
#define SCORE_W  20736      // 80 f32 row sums / exp values
#define SRED_W   20816      // 20 f32 reduction scratch
#define SMEM_WORDS 20836
#define SMEM_BYTES (SMEM_WORDS * 4)

__device__ float g_catep[BATCH * D_SZ];
__device__ int   g_mask_mode;                 // 0=u8, 1=i32, 2=f32
__device__ uint4 g_w1pk[32 * 16 * 32];        // 256 KB packed fp16 W hi/lo fragments
__device__ float g_pm[BATCH * 3];             // per-third local max
__device__ float g_pl[BATCH * 3];             // per-third local exp-sum
__device__ float g_pp[BATCH * 3 * D_SZ];      // per-third unnormalized pooled partials

__device__ __forceinline__ unsigned pack_hf2(float lo, float hi) {
    unsigned r;
    asm("cvt.rn.f16x2.f32 %0, %1, %2;" : "=r"(r) : "f"(hi), "f"(lo));
    return r;
}
__device__ __forceinline__ float hf_lo(unsigned w) { return __half2float(__ushort_as_half((unsigned short)(w & 0xFFFFu))); }
__device__ __forceinline__ float hf_hi(unsigned w) { return __half2float(__ushort_as_half((unsigned short)(w >> 16))); }
__device__ __forceinline__ float sigf(float x) { return __fdividef(1.0f, 1.0f + __expf(-x)); }

#define MMAF16(d, a0, a1, a2, a3, b0, b1)                                     \
    asm volatile("mma.sync.aligned.m16n8k16.row.col.f32.f16.f16.f32 "         \
                 "{%0,%1,%2,%3}, {%4,%5,%6,%7}, {%8,%9}, {%0,%1,%2,%3};"      \
                 : "+f"(d[0]), "+f"(d[1]), "+f"(d[2]), "+f"(d[3])             \
                 : "r"(a0), "r"(a1), "r"(a2), "r"(a3), "r"(b0), "r"(b1))

// ---------------------------------------------------------------------------
// Prep: blocks 0..255 = catep GEMM (fp32 exact, float4 W2 loads),
// 256 = W1 fp16 hi/lo fragment pack, 257 = mask dtype detection.
// ---------------------------------------------------------------------------
__global__ void prep_kernel(const float* __restrict__ cate,
                            const float* __restrict__ W2,
                            const float* __restrict__ b2,
                            const float* __restrict__ W1,
                            const unsigned* __restrict__ mw) {
    __shared__ float sm[16 * 256];
    __shared__ int   fl[2];
    const int blk = blockIdx.x, tid = threadIdx.x;

    if (blk < 256) {
        const int bbase = blk * 16;
        #pragma unroll
        for (int i = 0; i < 16; i++)
            sm[i * 256 + tid] = cate[(size_t)(bbase + i) * 256 + tid];
        __syncthreads();

        float acc[16];
        #pragma unroll
        for (int r = 0; r < 16; r++) acc[r] = 0.0f;
        const float4* w2row = (const float4*)(W2 + (size_t)tid * 256);
        #pragma unroll 2
        for (int k4 = 0; k4 < 64; k4++) {
            const float4 w = w2row[k4];
            #pragma unroll
            for (int r = 0; r < 16; r++) {
                const float* s4 = sm + r * 256 + k4 * 4;
                acc[r] += s4[0] * w.x + s4[1] * w.y + s4[2] * w.z + s4[3] * w.w;
            }
        }
        const float bias = b2[tid];
        #pragma unroll
        for (int r = 0; r < 16; r++)
            g_catep[(size_t)(bbase + r) * 256 + tid] = acc[r] + bias;
    } else if (blk == 256) {
        // entry e = (ntg*16 + kt)*32 + lane ; lane = qr*4 + qc
        for (int e = tid; e < 32 * 16 * 32; e += 256) {
            const int ntg = e >> 9, kt = (e >> 5) & 15, lane = e & 31;
            const int qr = lane >> 2, qc = lane & 3;
            const float* src = W1 + (size_t)(ntg * 8 + qr) * 256 + kt * 16 + 2 * qc;
            const float w0 = src[0], w1v = src[1], w8 = src[8], w9 = src[9];
            const unsigned h0 = pack_hf2(w0, w1v);
            const unsigned h1 = pack_hf2(w8, w9);
            const float2 f0 = __half22float2(*(const __half2*)&h0);
            const float2 f1 = __half22float2(*(const __half2*)&h1);
            const unsigned l0 = pack_hf2(w0 - f0.x, w1v - f0.y);
            const unsigned l1 = pack_hf2(w8 - f1.x, w9 - f1.y);
            g_w1pk[e] = make_uint4(h0, h1, l0, l1);
        }
    } else {
        if (tid == 0) { fl[0] = 0; fl[1] = 0; }
        __syncthreads();
        int lF = 0, lU = 0;
        for (int i = tid; i < 4096; i += 256) {
            const unsigned v = mw[i];
            if (v == 0x3F800000u) lF = 1;
            if (v & 0xFFFFFF00u)  lU = 1;
        }
        if (lF) fl[0] = 1;
        if (lU) fl[1] = 1;
        __syncthreads();
        if (tid == 0) g_mask_mode = fl[0] ? 2 : (fl[1] ? 0 : 1);
    }
}

// ---------------------------------------------------------------------------
// Balanced GEMM worker: warp covers ALL NMT m-tiles for one 32-wide n-strip.
// 3-term fp16: z = Xh@Wh + Xl@Wh + Xh@Wl
// ---------------------------------------------------------------------------
template <int NMT>
__device__ __forceinline__ void gemm_bal(const unsigned* __restrict__ sw,
                                         float* sScore, const float* sC,
                                         int n0, int lane) {
    const int qr = lane >> 2, qc = lane & 3;
    const int ntg0 = n0 >> 3;

    float acc[NMT][4][4];
    #pragma unroll
    for (int mt = 0; mt < NMT; mt++)
        #pragma unroll
        for (int j = 0; j < 4; j++)
            #pragma unroll
            for (int i = 0; i < 4; i++) acc[mt][j][i] = 0.0f;

    uint4 wq[4];
    #pragma unroll
    for (int j = 0; j < 4; j++)
        wq[j] = g_w1pk[(size_t)((ntg0 + j) * 16) * 32 + lane];

    #pragma unroll 1
    for (int kt = 0; kt < 16; kt++) {
        uint4 w[4];
        #pragma unroll
        for (int j = 0; j < 4; j++) w[j] = wq[j];
        if (kt < 15) {
            #pragma unroll
            for (int j = 0; j < 4; j++)
                wq[j] = g_w1pk[(size_t)((ntg0 + j) * 16 + kt + 1) * 32 + lane];
        }
        const unsigned abase = kt * 128 + lane * 4;
        #pragma unroll
        for (int mt = 0; mt < NMT; mt++) {
            const uint4 ah = *(const uint4*)(sw + XH_W + mt * 2048 + abase);
            const uint4 al = *(const uint4*)(sw + XL_W + mt * 2048 + abase);
            #pragma unroll
            for (int j = 0; j < 4; j++)
                MMAF16(acc[mt][j], ah.x, ah.y, ah.z, ah.w, w[j].x, w[j].y);
            #pragma unroll
            for (int j = 0; j < 4; j++)
                MMAF16(acc[mt][j], al.x, al.y, al.z, al.w, w[j].x, w[j].y);
            #pragma unroll
            for (int j = 0; j < 4; j++)
                MMAF16(acc[mt][j], ah.x, ah.y, ah.z, ah.w, w[j].z, w[j].w);
        }
    }

    float b0[4], b1[4];
    #pragma unroll
    for (int j = 0; j < 4; j++) {
        b0[j] = sC[n0 + j * 8 + 2 * qc];
        b1[j] = sC[n0 + j * 8 + 2 * qc + 1];
    }
    #pragma unroll
    for (int mt = 0; mt < NMT; mt++) {
        float v0 = 0.0f, v1 = 0.0f;
        #pragma unroll
        for (int j = 0; j < 4; j++) {
            v0 += sigf(acc[mt][j][0] + b0[j]) + sigf(acc[mt][j][1] + b1[j]);
            v1 += sigf(acc[mt][j][2] + b0[j]) + sigf(acc[mt][j][3] + b1[j]);
        }
        v0 += __shfl_xor_sync(0xffffffffu, v0, 1);
        v0 += __shfl_xor_sync(0xffffffffu, v0, 2);
        v1 += __shfl_xor_sync(0xffffffffu, v1, 1);
        v1 += __shfl_xor_sync(0xffffffffu, v1, 2);
        if (qc == 0) {
            atomicAdd(&sScore[mt * 16 + qr], v0);
            atomicAdd(&sScore[mt * 16 + qr + 8], v1);
        }
    }
}

// ---------------------------------------------------------------------------
// K_score: 3 CTAs per batch (rows 0-79 / 80-143 / 144-207). After scoring,
// computes local masked softmax + unnormalized pooled partial from SMEM X
// (flash-style two-level softmax; no seq re-read needed later).
// ---------------------------------------------------------------------------
__global__ void __launch_bounds__(256, 2)
score_kernel(const float* __restrict__ seq,
             const void*  __restrict__ maskp,
             const float* __restrict__ b1) {
    extern __shared__ unsigned sw[];
    const int bid = blockIdx.x;
    const int b = bid / 3, third = bid - 3 * b;
    const int r0  = (third == 0) ? 0 : (third == 1 ? 80 : 144);
    const int nmt = (third == 0) ? 5 : 4;
    const int nr  = nmt * 16;
    const int tid = threadIdx.x, warp = tid >> 5, lane = tid & 31;

    float* sC     = (float*)(sw + SC_W);
    float* sScore = (float*)(sw + SCORE_W);
    float* sRed   = (float*)(sw + SRED_W);

    // early mask load (rows >= S_SZ are padding -> masked)
    bool mk = true;
    if (tid < nr) {
        const int s = r0 + tid;
        if (s < S_SZ) {
            const size_t mi = (size_t)b * S_SZ + s;
            const int mode = g_mask_mode;
            if (mode == 0)      mk = ((const unsigned char*)maskp)[mi] != 0;
            else if (mode == 1) mk = ((const int*)maskp)[mi] != 0;
            else                mk = ((const float*)maskp)[mi] != 0.0f;
        }
    }

    sC[tid] = g_catep[(size_t)b * 256 + tid] + b1[tid];
    if (tid < 80) sScore[tid] = 0.0f;
    __syncthreads();

    // ---- P1: load rows [r0, r0+nr) + fp16 hi/lo split, fragment order ----
    {
        const float4* gsrc = (const float4*)(seq + (size_t)b * S_SZ * D_SZ);
        const int nidx = nr * 64;
        for (int idx = tid; idx < nidx; idx += 256) {
            const int lr = idx >> 6, c4 = idx & 63;
            const int g = r0 + lr;
            float4 v = make_float4(0.f, 0.f, 0.f, 0.f);
            if (g < S_SZ) v = gsrc[g * 64 + c4];
            const unsigned h01 = pack_hf2(v.x, v.y);
            const unsigned h23 = pack_hf2(v.z, v.w);
            const float2 f01 = __half22float2(*(const __half2*)&h01);
            const float2 f23 = __half22float2(*(const __half2*)&h23);
            const unsigned l01 = pack_hf2(v.x - f01.x, v.y - f01.y);
            const unsigned l23 = pack_hf2(v.z - f23.x, v.w - f23.y);
            const int cp = 2 * c4, rr = cp & 7;
            const int r16 = lr & 15;
            const int widx = (lr >> 4) * 2048 + (cp >> 3) * 128
                           + (r16 & 7) * 16 + (rr & 3) * 4 + (rr >> 2) * 2 + (r16 >> 3);
            sw[XH_W + widx]     = h01;
            sw[XH_W + widx + 4] = h23;
            sw[XL_W + widx]     = l01;
            sw[XL_W + widx + 4] = l23;
        }
    }
    __syncthreads();

    // ---- P2: balanced GEMM, warp n-strip [warp*32, warp*32+32) ----
    if (nmt == 5) gemm_bal<5>(sw, sScore, sC, warp * 32, lane);
    else          gemm_bal<4>(sw, sScore, sC, warp * 32, lane);
    __syncthreads();

    // ---- P3: local masked softmax over nr rows ----
    float sv = (tid < nr) ? (mk ? -1e9f : sScore[tid]) : -3.4e38f;

    float m = sv;
    #pragma unroll
    for (int o = 16; o > 0; o >>= 1) m = fmaxf(m, __shfl_xor_sync(0xffffffffu, m, o));
    if (lane == 0) sRed[warp] = m;
    __syncthreads();
    if (warp == 0) {
        float t = (lane < 8) ? sRed[lane] : -3.4e38f;
        #pragma unroll
        for (int o = 16; o > 0; o >>= 1) t = fmaxf(t, __shfl_xor_sync(0xffffffffu, t, o));
        if (lane == 0) sRed[16] = t;
    }
    __syncthreads();
    m = sRed[16];

    const float ev = (tid < nr) ? __expf(sv - m) : 0.0f;
    float l = ev;
    #pragma unroll
    for (int o = 16; o > 0; o >>= 1) l += __shfl_xor_sync(0xffffffffu, l, o);
    if (lane == 0) sRed[warp] = l;
    __syncthreads();
    if (warp == 0) {
        float u = (lane < 8) ? sRed[lane] : 0.0f;
        #pragma unroll
        for (int o = 16; o > 0; o >>= 1) u += __shfl_xor_sync(0xffffffffu, u, o);
        if (lane == 0) sRed[17] = u;
    }
    __syncthreads();                 // sScore reads done; sRed[17] final
    if (tid < nr) sScore[tid] = ev;
    __syncthreads();

    // ---- P4: unnormalized pooled partial from SMEM X (x = hi + lo) ----
    {
        const int cp = tid >> 1, hl = tid & 1;
        const int Cd = (cp >> 3) * 128 + (cp & 3) * 4 + ((cp & 7) >> 2) * 2;
        float accd = 0.0f;
        #pragma unroll 4
        for (int s = 0; s < nr; s++) {
            const int fs = (s >> 4) * 2048 + (s & 7) * 16 + ((s & 15) >> 3);
            const unsigned wh = sw[XH_W + Cd + fs];
            const unsigned wl = sw[XL_W + Cd + fs];
            const float x = (hl ? hf_hi(wh) : hf_lo(wh)) + (hl ? hf_hi(wl) : hf_lo(wl));
            accd += sScore[s] * x;
        }
        g_pp[(size_t)(b * 3 + third) * 256 + tid] = accd;
        if (tid == 0) {
            g_pm[b * 3 + third] = m;
            g_pl[b * 3 + third] = sRed[17];
        }
    }
}

// ---------------------------------------------------------------------------
// K_combine: merge the 3 thirds -- global max, rescale, normalize.
// ---------------------------------------------------------------------------
__global__ void __launch_bounds__(256)
combine_kernel(float* __restrict__ out) {
    const int b = blockIdx.x, tid = threadIdx.x;
    const float m0 = g_pm[b * 3], m1 = g_pm[b * 3 + 1], m2 = g_pm[b * 3 + 2];
    const float m  = fmaxf(m0, fmaxf(m1, m2));
    const float w0 = __expf(m0 - m), w1 = __expf(m1 - m), w2 = __expf(m2 - m);
    const float L  = w0 * g_pl[b * 3] + w1 * g_pl[b * 3 + 1] + w2 * g_pl[b * 3 + 2];
    const float inv = 1.0f / L;
    const float p = w0 * g_pp[(size_t)(b * 3) * 256 + tid]
                  + w1 * g_pp[(size_t)(b * 3 + 1) * 256 + tid]
                  + w2 * g_pp[(size_t)(b * 3 + 2) * 256 + tid];
    out[(size_t)b * 256 + tid] = p * inv;
}

// ---------------------------------------------------------------------------
extern "C" void kernel_launch(void* const* d_in, const int* in_sizes, int n_in,
                              void* d_out, int out_size) {
    const float* cate = (const float*)d_in[0];
    const float* seq  = (const float*)d_in[1];
    const void*  mask = d_in[2];
    const float* W1   = (const float*)d_in[3];
    const float* b1   = (const float*)d_in[4];
    const float* W2   = (const float*)d_in[5];
    const float* b2   = (const float*)d_in[6];
    float*       out  = (float*)d_out;

    cudaFuncSetAttribute(score_kernel,
                         cudaFuncAttributeMaxDynamicSharedMemorySize, SMEM_BYTES);

    prep_kernel<<<258, 256>>>(cate, W2, b2, W1, (const unsigned*)mask);
    score_kernel<<<3 * BATCH, 256, SMEM_BYTES>>>(seq, mask, b1);
    combine_kernel<<<BATCH, 256>>>(out);
}